// round 15
// baseline (speedup 1.0000x reference)
#include <cuda_runtime.h>
#include <cuda_fp16.h>
#include <cstdint>

// ============================================================================
// out[b,o,e] = sum_{c,k} G[b,c,e,k] * W[o,c,k] + bias[o]
//   G taps: [self, n0+n2, n1+n3, |n0-n2|, |n1-n3|]
// GEMM [COUT=256] x [K'=640] x [B*E=120000], fp16 operands / fp32 accum.
// f32-accum mma.sync.m16n8k16 @ rt=16 — pipe measured ~100% saturated in this
// config (f16-accum rt=8 exists but loses to smem-bandwidth/register walls;
// falsified in R13/R14). CTA = 64 edges x 128 outs, 256 thr, 2 CTAs/SM.
// 5 merged K=128 stages (tap order 0,1,3,2,4); pair stages share gathers.
// Prep: single merged launch (transpose slices y<4, wprep slice y==4).
// ============================================================================
static constexpr int BATCH = 4;
static constexpr int CIN   = 128;
static constexpr int COUT  = 256;
static constexpr int E     = 30000;
static constexpr int TAPS  = 5;

static constexpr int MTILE   = 64;                        // edges per CTA
static constexpr int ETILES  = (E + MTILE - 1) / MTILE;   // 469
static constexpr int NBLOCKS = BATCH * ETILES * 2;        // 3752 (x2 n-halves)

// tap order: 0,1,3,2,4
#define STAGE_TAP(pos) ((int)((0x42310u >> ((pos) * 4)) & 0xF))

// ============================================================================
// Device scratch
// ============================================================================
__device__ __half g_xt16[(size_t)BATCH * E * CIN];   // x transposed [B,E,C] fp16
__device__ __half g_w[TAPS * 2 * COUT * 64];         // [tap][khalf][n][64]

// ============================================================================
// Helpers
// ============================================================================
__device__ __forceinline__ uint32_t smem_u32(const void* p) {
    uint32_t a;
    asm("{ .reg .u64 t; cvta.to.shared.u64 t, %1; cvt.u32.u64 %0, t; }"
        : "=r"(a) : "l"(p));
    return a;
}

#define SMEM_SWIZZLE_128B(off) ((off) ^ (((off) >> 3) & 0x70))

__device__ __forceinline__ void ldsm_x4(uint32_t& r0, uint32_t& r1,
                                        uint32_t& r2, uint32_t& r3, uint32_t addr) {
    asm volatile("ldmatrix.sync.aligned.m8n8.x4.shared.b16 {%0,%1,%2,%3}, [%4];"
                 : "=r"(r0), "=r"(r1), "=r"(r2), "=r"(r3) : "r"(addr));
}

__device__ __forceinline__ void mma16816(float* c, const uint32_t* a, const uint32_t* b) {
    asm volatile(
        "mma.sync.aligned.m16n8k16.row.col.f32.f16.f16.f32 "
        "{%0,%1,%2,%3}, {%4,%5,%6,%7}, {%8,%9}, {%0,%1,%2,%3};"
        : "+f"(c[0]), "+f"(c[1]), "+f"(c[2]), "+f"(c[3])
        : "r"(a[0]), "r"(a[1]), "r"(a[2]), "r"(a[3]), "r"(b[0]), "r"(b[1]));
}

__device__ __forceinline__ uint32_t pack_half2(float a, float b) {
    __half2 h = __floats2half2_rn(a, b);
    return *(uint32_t*)&h;
}

__device__ __forceinline__ void cp_async16(uint32_t dst, const void* src) {
    asm volatile("cp.async.cg.shared.global [%0], [%1], 16;" :: "r"(dst), "l"(src));
}
__device__ __forceinline__ void cp_async16_zfill(uint32_t dst, const void* src) {
    asm volatile("cp.async.cg.shared.global [%0], [%1], 16, 0;" :: "r"(dst), "l"(src));
}
#define CP_COMMIT() asm volatile("cp.async.commit_group;")
#define CP_WAIT0()  asm volatile("cp.async.wait_group 0;" ::: "memory")

// half2 vector combine on uint4 (8 halves)
__device__ __forceinline__ uint4 h2_add4(uint4 a, uint4 b) {
    uint4 r;
    #pragma unroll
    for (int i = 0; i < 4; ++i)
        ((__half2*)&r)[i] = __hadd2(((const __half2*)&a)[i], ((const __half2*)&b)[i]);
    return r;
}
__device__ __forceinline__ uint4 h2_absdiff4(uint4 a, uint4 b) {
    uint4 r;
    #pragma unroll
    for (int i = 0; i < 4; ++i)
        ((__half2*)&r)[i] = __habs2(__hsub2(((const __half2*)&a)[i], ((const __half2*)&b)[i]));
    return r;
}

// ============================================================================
// Prep (merged): y<4 -> transpose x [B,C,E] f32 -> g_xt16 [B,E,C] fp16
// (128e x 32c tiles, XOR-swizzled 16KB smem); y==4 -> conv_w fp16 convert.
// ============================================================================
__global__ void prep_kernel(const float* __restrict__ x,
                            const float* __restrict__ w) {
    __shared__ uint4 tile4[32 * 32];          // 16 KB
    const int tid = threadIdx.x;              // 256

    if (blockIdx.y == 4) {
        const int wblk = blockIdx.z * 235 + blockIdx.x;
        if (wblk < 640) {
            const int idx = wblk * 256 + tid;     // < 163840
            const int tap = idx % TAPS;
            const int c   = (idx / TAPS) % CIN;
            const int n   = idx / (TAPS * CIN);
            const int kh = c >> 6, j = c & 63;
            g_w[((tap * 2 + kh) * COUT + n) * 64 + j] = __float2half_rn(w[idx]);
        }
        return;
    }

    const int b  = blockIdx.z;
    const int c0 = blockIdx.y * 32;
    const int e0 = blockIdx.x * 128;

    #pragma unroll
    for (int i = 0; i < 4; ++i) {
        const int idx = tid + i * 256;
        const int c = idx >> 5;
        const int j = idx & 31;
        const int e = e0 + j * 4;
        float4 v = make_float4(0.f, 0.f, 0.f, 0.f);
        if (e < E)   // E % 4 == 0
            v = *(const float4*)(x + ((size_t)b * CIN + c0 + c) * E + e);
        tile4[c * 32 + (j ^ ((c >> 3) & 3))] = *(const uint4*)&v;
    }
    __syncthreads();

    const float* tf = (const float*)tile4;
    #pragma unroll
    for (int i = 0; i < 2; ++i) {
        const int idx = tid + i * 256;
        const int e = idx >> 2;
        const int g = (idx & 3) * 8;
        if (e0 + e < E) {
            uint4 v;
            uint32_t* pv = (uint32_t*)&v;
            const int j  = e >> 2;
            const int el = e & 3;
            #pragma unroll
            for (int h = 0; h < 4; ++h) {
                const int ca = g + 2 * h;
                const int jx = (j ^ ((ca >> 3) & 3)) * 4 + el;
                pv[h] = pack_half2(tf[ca * 128 + jx], tf[(ca + 1) * 128 + jx]);
            }
            *(uint4*)(g_xt16 + ((size_t)b * E + e0 + e) * CIN + c0 + g) = v;
        }
    }
}

// ============================================================================
// Main kernel: 256 threads, 8 warps (2m x 4n), warp tile 32m x 32n.
// A tile 64m x 128k fp16 = 2 x 8KB khalf sub-tiles (SW128 each), 3-slot ring.
// B tile 128n x 128k fp16 = 2 x 16KB khalf sub-tiles, double buffered.
// smem 115200 B -> 2 CTAs/SM. (Proven 127.5us config from R12.)
// ============================================================================
static constexpr int SMEM_BIAS = 0;                 // 512 B (128 floats)
static constexpr int SMEM_A    = 512;               // 3 slots x 16 KB
static constexpr int SMEM_B    = 512 + 3 * 16384;   // 2 bufs x 32 KB
static constexpr int SMEM_TOTAL = SMEM_B + 2 * 32768;   // 115200 B

#define A_H(slot) (SMEM_A + (slot) * 16384)
#define B_H(buf)  (SMEM_B + (buf) * 32768)

__global__ void __launch_bounds__(256, 2) mesh_main(
    const int* __restrict__ ne_idx,
    const float* __restrict__ bias,
    float* __restrict__ out)
{
    extern __shared__ char smem[];
    const uint32_t smem_base = smem_u32(smem);
    const int tid  = threadIdx.x;
    const int wid  = tid >> 5;
    const int lane = tid & 31;

    const int blk    = blockIdx.x;
    const int b      = blk / (ETILES * 2);
    const int rem    = blk % (ETILES * 2);
    const int et     = rem >> 1;
    const int nh     = rem & 1;               // n-half: outputs [nh*128, +128)
    const int ebase  = et * MTILE;
    const int evalid = min(MTILE, E - ebase);

    if (tid < 128) ((float*)(smem + SMEM_BIAS))[tid] = bias[nh * 128 + tid];

    const int warp_m = wid & 1;
    const int warp_n = wid >> 1;
    const int m0w = warp_m * 32;
    const int n0w = warp_n * 32;

    float acc[2][4][4];
    #pragma unroll
    for (int i = 0; i < 2; ++i)
        #pragma unroll
        for (int j = 0; j < 4; ++j)
            #pragma unroll
            for (int q = 0; q < 4; ++q) acc[i][j][q] = 0.f;

    const __half* xtb = g_xt16 + (size_t)b * E * CIN;
    const int*    nb  = ne_idx + ((size_t)b * E + ebase) * 4;

    // ldmatrix lane addressing
    const int a_row = lane & 15;
    const int a_kof = (lane >> 4) << 3;
    const int b_row = (lane & 7) + ((lane & 16) ? 8 : 0);
    const int b_kof = (lane & 8) ? 8 : 0;

    // gather fill mapping: 16 threads/edge, 8 fp16 channels/thread
    const int gj0 = (tid & 15) * 8;
    const int gm0 = tid >> 4;                  // edge within 16-edge pass
    const uint32_t g_koff = (uint32_t)(gj0 >> 6) * 8192;    // khalf sub-tile

    const int bnrow = nh * 128;                // B source row base for n-half

    // ---------------- Prologue: B(tap0) + A slot0 (self rows, contiguous) ----
    {
        #pragma unroll
        for (int q = 0; q < 8; ++q) {          // B: 2048 x 16B
            int i = tid + q * 256;
            const int kh = i >> 10;
            const int r  = (i & 1023) >> 3;
            const int c  = i & 7;
            uint32_t off = (uint32_t)kh * 16384 +
                SMEM_SWIZZLE_128B((uint32_t)(r * 128 + c * 16));
            const __half* src = g_w + ((size_t)kh * COUT + bnrow + r) * 64 + c * 8;
            cp_async16(smem_base + B_H(0) + off, src);
        }
        #pragma unroll
        for (int q = 0; q < 4; ++q) {          // A: 1024 x 16B
            int i = tid + q * 256;
            const int m = i >> 4;
            const int part = i & 15;
            uint32_t off = (uint32_t)(part >> 3) * 8192 +
                SMEM_SWIZZLE_128B((uint32_t)(m * 128 + (part & 7) * 16));
            const __half* src = xtb + (size_t)(ebase + m) * CIN + part * 8;
            if (m < evalid) cp_async16(smem_base + A_H(0) + off, src);
            else            cp_async16_zfill(smem_base + A_H(0) + off, xtb);
        }
        CP_COMMIT();
        CP_WAIT0();
        __syncthreads();
    }

    // ---------------- 5 merged stages (fully unrolled) ----------------
    #pragma unroll
    for (int s = 0; s < 5; ++s) {
        const int slot = s % 3;
        const int buf  = s & 1;
        const bool do_fill = (s == 0) || (s == 2);
        const int slotS = (s + 1) % 3;
        const int slotA = (s + 2) % 3;
        const bool useXZ = (s == 0);

        // B fill for next stage
        if (s < 4) {
            const __half* srcB = g_w + (size_t)STAGE_TAP(s + 1) * (2 * COUT * 64);
            const uint32_t dB = smem_base + B_H(buf ^ 1);
            #pragma unroll
            for (int q = 0; q < 8; ++q) {
                int i = tid + q * 256;
                const int kh = i >> 10;
                const int r  = (i & 1023) >> 3;
                const int c  = i & 7;
                uint32_t off = (uint32_t)kh * 16384 +
                    SMEM_SWIZZLE_128B((uint32_t)(r * 128 + c * 16));
                cp_async16(dB + off, srcB + ((size_t)kh * COUT + bnrow + r) * 64 + c * 8);
            }
            CP_COMMIT();
        }

        const uint32_t aB = smem_base + A_H(slot);
        const uint32_t bB = smem_base + B_H(buf);

        // gather prefetch for pass 0
        uint4 ga = make_uint4(0, 0, 0, 0);
        uint4 gc = make_uint4(0, 0, 0, 0);
        if (do_fill && gm0 < evalid) {
            const int4 nbr = *(const int4*)(nb + gm0 * 4);
            const int ia = useXZ ? nbr.x : nbr.y;
            const int ib = useXZ ? nbr.z : nbr.w;
            ga = *(const uint4*)(xtb + (size_t)ia * CIN + gj0);
            gc = *(const uint4*)(xtb + (size_t)ib * CIN + gj0);
        }

        #pragma unroll
        for (int kk = 0; kk < 8; ++kk) {
            // prefetch gathers for pass kk+1
            uint4 gan = make_uint4(0, 0, 0, 0);
            uint4 gcn = make_uint4(0, 0, 0, 0);
            if (do_fill && kk < 3) {
                const int gm = (kk + 1) * 16 + gm0;
                if (gm < evalid) {
                    const int4 nbr = *(const int4*)(nb + gm * 4);
                    const int ia = useXZ ? nbr.x : nbr.y;
                    const int ib = useXZ ? nbr.z : nbr.w;
                    gan = *(const uint4*)(xtb + (size_t)ia * CIN + gj0);
                    gcn = *(const uint4*)(xtb + (size_t)ib * CIN + gj0);
                }
            }

            // ---- compute chunk kk: 8 HMMA ----
            {
                const uint32_t akh = (uint32_t)(kk >> 2) * 8192;
                const uint32_t bkh = (uint32_t)(kk >> 2) * 16384;
                const int kc = (kk & 3) * 16;
                uint32_t ah[2][4], bf[4][2];
                #pragma unroll
                for (int mt = 0; mt < 2; ++mt) {
                    const int row = m0w + mt * 16 + a_row;
                    uint32_t off = SMEM_SWIZZLE_128B((uint32_t)(row * 128 + (kc + a_kof) * 2));
                    ldsm_x4(ah[mt][0], ah[mt][1], ah[mt][2], ah[mt][3], aB + akh + off);
                }
                #pragma unroll
                for (int nbq = 0; nbq < 2; ++nbq) {
                    const int row = n0w + nbq * 16 + b_row;
                    uint32_t off = SMEM_SWIZZLE_128B((uint32_t)(row * 128 + (kc + b_kof) * 2));
                    ldsm_x4(bf[nbq * 2][0], bf[nbq * 2][1],
                            bf[nbq * 2 + 1][0], bf[nbq * 2 + 1][1], bB + bkh + off);
                }
                #pragma unroll
                for (int mt = 0; mt < 2; ++mt)
                    #pragma unroll
                    for (int j = 0; j < 4; ++j) mma16816(acc[mt][j], ah[mt], bf[j]);
            }

            // ---- combine + STS for pass kk (sum -> slotS, abs -> slotA) ----
            if (do_fill && kk < 4) {
                const int gm = kk * 16 + gm0;
                const uint32_t off = g_koff +
                    SMEM_SWIZZLE_128B((uint32_t)(gm * 128 + (gj0 & 63) * 2));
                *(uint4*)(smem + A_H(slotS) + off) = h2_add4(ga, gc);
                *(uint4*)(smem + A_H(slotA) + off) = h2_absdiff4(ga, gc);
                ga = gan; gc = gcn;
            }
        }

        if (s < 4) {
            CP_WAIT0();
            __syncthreads();
        }
    }

    // ---------------- Epilogue: +bias, store out[b][nh*128 + o][e] ----------
    {
        const float* bsm = (const float*)(smem + SMEM_BIAS);
        float* obase = out + ((size_t)b * COUT + nh * 128) * E;
        #pragma unroll
        for (int mt = 0; mt < 2; ++mt) {
            const int r0 = m0w + mt * 16 + (lane >> 2);
            const int r1 = r0 + 8;
            const bool ok0 = r0 < evalid;
            const bool ok1 = r1 < evalid;
            #pragma unroll
            for (int j = 0; j < 4; ++j) {
                const int o = n0w + j * 8 + 2 * (lane & 3);
                const float b0 = bsm[o], b1 = bsm[o + 1];
                float* p0 = obase + (size_t)o * E;
                float* p1 = obase + (size_t)(o + 1) * E;
                if (ok0) {
                    p0[ebase + r0] = acc[mt][j][0] + b0;
                    p1[ebase + r0] = acc[mt][j][1] + b1;
                }
                if (ok1) {
                    p0[ebase + r1] = acc[mt][j][2] + b0;
                    p1[ebase + r1] = acc[mt][j][3] + b1;
                }
            }
        }
    }
}

// ============================================================================
// Launch
// ============================================================================
extern "C" void kernel_launch(void* const* d_in, const int* in_sizes, int n_in,
                              void* d_out, int out_size) {
    const float* x    = (const float*)d_in[0];
    const int*   ne   = (const int*)d_in[1];
    const float* w    = (const float*)d_in[2];
    const float* bias = (const float*)d_in[3];
    float*       out  = (float*)d_out;

    cudaFuncSetAttribute(mesh_main, cudaFuncAttributeMaxDynamicSharedMemorySize, SMEM_TOTAL);

    dim3 pgrid((E + 127) / 128, 5, BATCH);    // y<4: transpose; y==4: wprep
    prep_kernel<<<pgrid, 256>>>(x, w);
    mesh_main<<<NBLOCKS, 256, SMEM_TOTAL>>>(ne, bias, out);
}

// round 16
// speedup vs baseline: 1.4774x; 1.4774x over previous
#include <cuda_runtime.h>
#include <cuda_fp16.h>
#include <cstdint>

// ============================================================================
// out[b,o,e] = sum_{c,k} G[b,c,e,k] * W[o,c,k] + bias[o]
//   G taps: [self, n0+n2, n1+n3, |n0-n2|, |n1-n3|]
// GEMM [COUT=256] x [K'=640] x [B*E=120000], fp16 operands / fp32 accum.
// CTA = 64 edges x 128 outputs (N split in 2) so smem fits 2 CTAs/SM:
// hides per-CTA prologue under the co-resident CTA's MMAs and cuts wave
// quantization. f32-accum mma.sync pipe measured ~100% saturated here.
// 5 merged K=128 stages (tap order 0,1,3,2,4); pair stages share gathers.
// EXACT resubmission of the measured-145.9us R12 artifact (R15's 215us on
// identical mesh_main code attributed to a slow-clocked federation host).
// ============================================================================
static constexpr int BATCH = 4;
static constexpr int CIN   = 128;
static constexpr int COUT  = 256;
static constexpr int E     = 30000;
static constexpr int TAPS  = 5;

static constexpr int MTILE   = 64;                        // edges per CTA
static constexpr int ETILES  = (E + MTILE - 1) / MTILE;   // 469
static constexpr int NBLOCKS = BATCH * ETILES * 2;        // 3752 (x2 n-halves)

// tap order: 0,1,3,2,4
#define STAGE_TAP(pos) ((int)((0x42310u >> ((pos) * 4)) & 0xF))

// ============================================================================
// Device scratch
// ============================================================================
__device__ __half g_xt16[(size_t)BATCH * E * CIN];   // x transposed [B,E,C] fp16
__device__ __half g_w[TAPS * 2 * COUT * 64];         // [tap][khalf][n][64]

// ============================================================================
// Helpers
// ============================================================================
__device__ __forceinline__ uint32_t smem_u32(const void* p) {
    uint32_t a;
    asm("{ .reg .u64 t; cvta.to.shared.u64 t, %1; cvt.u32.u64 %0, t; }"
        : "=r"(a) : "l"(p));
    return a;
}

#define SMEM_SWIZZLE_128B(off) ((off) ^ (((off) >> 3) & 0x70))

__device__ __forceinline__ void ldsm_x4(uint32_t& r0, uint32_t& r1,
                                        uint32_t& r2, uint32_t& r3, uint32_t addr) {
    asm volatile("ldmatrix.sync.aligned.m8n8.x4.shared.b16 {%0,%1,%2,%3}, [%4];"
                 : "=r"(r0), "=r"(r1), "=r"(r2), "=r"(r3) : "r"(addr));
}

__device__ __forceinline__ void mma16816(float* c, const uint32_t* a, const uint32_t* b) {
    asm volatile(
        "mma.sync.aligned.m16n8k16.row.col.f32.f16.f16.f32 "
        "{%0,%1,%2,%3}, {%4,%5,%6,%7}, {%8,%9}, {%0,%1,%2,%3};"
        : "+f"(c[0]), "+f"(c[1]), "+f"(c[2]), "+f"(c[3])
        : "r"(a[0]), "r"(a[1]), "r"(a[2]), "r"(a[3]), "r"(b[0]), "r"(b[1]));
}

__device__ __forceinline__ uint32_t pack_half2(float a, float b) {
    __half2 h = __floats2half2_rn(a, b);
    return *(uint32_t*)&h;
}

__device__ __forceinline__ void cp_async16(uint32_t dst, const void* src) {
    asm volatile("cp.async.cg.shared.global [%0], [%1], 16;" :: "r"(dst), "l"(src));
}
__device__ __forceinline__ void cp_async16_zfill(uint32_t dst, const void* src) {
    asm volatile("cp.async.cg.shared.global [%0], [%1], 16, 0;" :: "r"(dst), "l"(src));
}
#define CP_COMMIT() asm volatile("cp.async.commit_group;")
#define CP_WAIT0()  asm volatile("cp.async.wait_group 0;" ::: "memory")

// half2 vector combine on uint4 (8 halves)
__device__ __forceinline__ uint4 h2_add4(uint4 a, uint4 b) {
    uint4 r;
    #pragma unroll
    for (int i = 0; i < 4; ++i)
        ((__half2*)&r)[i] = __hadd2(((const __half2*)&a)[i], ((const __half2*)&b)[i]);
    return r;
}
__device__ __forceinline__ uint4 h2_absdiff4(uint4 a, uint4 b) {
    uint4 r;
    #pragma unroll
    for (int i = 0; i < 4; ++i)
        ((__half2*)&r)[i] = __habs2(__hsub2(((const __half2*)&a)[i], ((const __half2*)&b)[i]));
    return r;
}

// ============================================================================
// Prep 1: transpose x [B,C,E] f32 -> g_xt16 [B,E,C] fp16. 128e x 32c tiles,
// uint4[32][32] with XOR swizzle (proven 16.8us config).
// ============================================================================
__global__ void transpose_kernel(const float* __restrict__ x) {
    __shared__ uint4 tile4[32 * 32];          // 16 KB
    const int b  = blockIdx.z;
    const int c0 = blockIdx.y * 32;
    const int e0 = blockIdx.x * 128;
    const int tid = threadIdx.x;              // 256

    #pragma unroll
    for (int i = 0; i < 4; ++i) {
        const int idx = tid + i * 256;
        const int c = idx >> 5;
        const int j = idx & 31;
        const int e = e0 + j * 4;
        float4 v = make_float4(0.f, 0.f, 0.f, 0.f);
        if (e < E)   // E % 4 == 0
            v = *(const float4*)(x + ((size_t)b * CIN + c0 + c) * E + e);
        tile4[c * 32 + (j ^ ((c >> 3) & 3))] = *(const uint4*)&v;
    }
    __syncthreads();

    const float* tf = (const float*)tile4;
    #pragma unroll
    for (int i = 0; i < 2; ++i) {
        const int idx = tid + i * 256;
        const int e = idx >> 2;
        const int g = (idx & 3) * 8;
        if (e0 + e < E) {
            uint4 v;
            uint32_t* pv = (uint32_t*)&v;
            const int j  = e >> 2;
            const int el = e & 3;
            #pragma unroll
            for (int h = 0; h < 4; ++h) {
                const int ca = g + 2 * h;
                const int jx = (j ^ ((ca >> 3) & 3)) * 4 + el;
                pv[h] = pack_half2(tf[ca * 128 + jx], tf[(ca + 1) * 128 + jx]);
            }
            *(uint4*)(g_xt16 + ((size_t)b * E + e0 + e) * CIN + c0 + g) = v;
        }
    }
}

// ============================================================================
// Prep 2: convert conv_w to fp16, [tap][khalf][n][64] k-major layout
// ============================================================================
__global__ void wprep_kernel(const float* __restrict__ w) {
    int idx = blockIdx.x * 256 + threadIdx.x;
    if (idx >= COUT * CIN * TAPS) return;
    int tap = idx % TAPS;
    int c   = (idx / TAPS) % CIN;
    int n   = idx / (TAPS * CIN);
    int kh = c >> 6, j = c & 63;
    g_w[((tap * 2 + kh) * COUT + n) * 64 + j] = __float2half_rn(w[idx]);
}

// ============================================================================
// Main kernel: 256 threads, 8 warps (2m x 4n), warp tile 32m x 32n.
// A tile 64m x 128k fp16 = 2 x 8KB khalf sub-tiles (SW128 each), 3-slot ring.
// B tile 128n x 128k fp16 = 2 x 16KB khalf sub-tiles, double buffered.
// smem 115200 B -> 2 CTAs/SM.
// ============================================================================
static constexpr int SMEM_BIAS = 0;                 // 512 B (128 floats)
static constexpr int SMEM_A    = 512;               // 3 slots x 16 KB
static constexpr int SMEM_B    = 512 + 3 * 16384;   // 2 bufs x 32 KB
static constexpr int SMEM_TOTAL = SMEM_B + 2 * 32768;   // 115200 B

#define A_H(slot) (SMEM_A + (slot) * 16384)
#define B_H(buf)  (SMEM_B + (buf) * 32768)

__global__ void __launch_bounds__(256, 2) mesh_main(
    const int* __restrict__ ne_idx,
    const float* __restrict__ bias,
    float* __restrict__ out)
{
    extern __shared__ char smem[];
    const uint32_t smem_base = smem_u32(smem);
    const int tid  = threadIdx.x;
    const int wid  = tid >> 5;
    const int lane = tid & 31;

    const int blk    = blockIdx.x;
    const int b      = blk / (ETILES * 2);
    const int rem    = blk % (ETILES * 2);
    const int et     = rem >> 1;
    const int nh     = rem & 1;               // n-half: outputs [nh*128, nh*128+128)
    const int ebase  = et * MTILE;
    const int evalid = min(MTILE, E - ebase);

    if (tid < 128) ((float*)(smem + SMEM_BIAS))[tid] = bias[nh * 128 + tid];

    const int warp_m = wid & 1;
    const int warp_n = wid >> 1;
    const int m0w = warp_m * 32;
    const int n0w = warp_n * 32;

    float acc[2][4][4];
    #pragma unroll
    for (int i = 0; i < 2; ++i)
        #pragma unroll
        for (int j = 0; j < 4; ++j)
            #pragma unroll
            for (int q = 0; q < 4; ++q) acc[i][j][q] = 0.f;

    const __half* xtb = g_xt16 + (size_t)b * E * CIN;
    const int*    nb  = ne_idx + ((size_t)b * E + ebase) * 4;

    // ldmatrix lane addressing
    const int a_row = lane & 15;
    const int a_kof = (lane >> 4) << 3;
    const int b_row = (lane & 7) + ((lane & 16) ? 8 : 0);
    const int b_kof = (lane & 8) ? 8 : 0;

    // gather fill mapping: 16 threads/edge, 8 fp16 channels/thread
    const int gj0 = (tid & 15) * 8;
    const int gm0 = tid >> 4;                  // edge within 16-edge pass
    const uint32_t g_koff = (uint32_t)(gj0 >> 6) * 8192;    // khalf sub-tile

    // B source row base for this n-half
    const int bnrow = nh * 128;

    // ---------------- Prologue: B(tap0) + A slot0 (self rows, contiguous) ----
    {
        #pragma unroll
        for (int q = 0; q < 8; ++q) {          // B: 2048 x 16B
            int i = tid + q * 256;
            const int kh = i >> 10;
            const int r  = (i & 1023) >> 3;
            const int c  = i & 7;
            uint32_t off = (uint32_t)kh * 16384 +
                SMEM_SWIZZLE_128B((uint32_t)(r * 128 + c * 16));
            const __half* src = g_w + ((size_t)kh * COUT + bnrow + r) * 64 + c * 8;
            cp_async16(smem_base + B_H(0) + off, src);
        }
        #pragma unroll
        for (int q = 0; q < 4; ++q) {          // A: 1024 x 16B
            int i = tid + q * 256;
            const int m = i >> 4;
            const int part = i & 15;
            uint32_t off = (uint32_t)(part >> 3) * 8192 +
                SMEM_SWIZZLE_128B((uint32_t)(m * 128 + (part & 7) * 16));
            const __half* src = xtb + (size_t)(ebase + m) * CIN + part * 8;
            if (m < evalid) cp_async16(smem_base + A_H(0) + off, src);
            else            cp_async16_zfill(smem_base + A_H(0) + off, xtb);
        }
        CP_COMMIT();
        CP_WAIT0();
        __syncthreads();
    }

    // ---------------- 5 merged stages (fully unrolled) ----------------
    #pragma unroll
    for (int s = 0; s < 5; ++s) {
        const int slot = s % 3;
        const int buf  = s & 1;
        const bool do_fill = (s == 0) || (s == 2);
        const int slotS = (s + 1) % 3;
        const int slotA = (s + 2) % 3;
        const bool useXZ = (s == 0);

        // B fill for next stage
        if (s < 4) {
            const __half* srcB = g_w + (size_t)STAGE_TAP(s + 1) * (2 * COUT * 64);
            const uint32_t dB = smem_base + B_H(buf ^ 1);
            #pragma unroll
            for (int q = 0; q < 8; ++q) {
                int i = tid + q * 256;
                const int kh = i >> 10;
                const int r  = (i & 1023) >> 3;
                const int c  = i & 7;
                uint32_t off = (uint32_t)kh * 16384 +
                    SMEM_SWIZZLE_128B((uint32_t)(r * 128 + c * 16));
                cp_async16(dB + off, srcB + ((size_t)kh * COUT + bnrow + r) * 64 + c * 8);
            }
            CP_COMMIT();
        }

        const uint32_t aB = smem_base + A_H(slot);
        const uint32_t bB = smem_base + B_H(buf);

        // gather prefetch for pass 0
        uint4 ga = make_uint4(0, 0, 0, 0);
        uint4 gc = make_uint4(0, 0, 0, 0);
        if (do_fill && gm0 < evalid) {
            const int4 nbr = *(const int4*)(nb + gm0 * 4);
            const int ia = useXZ ? nbr.x : nbr.y;
            const int ib = useXZ ? nbr.z : nbr.w;
            ga = *(const uint4*)(xtb + (size_t)ia * CIN + gj0);
            gc = *(const uint4*)(xtb + (size_t)ib * CIN + gj0);
        }

        #pragma unroll
        for (int kk = 0; kk < 8; ++kk) {
            // prefetch gathers for pass kk+1
            uint4 gan = make_uint4(0, 0, 0, 0);
            uint4 gcn = make_uint4(0, 0, 0, 0);
            if (do_fill && kk < 3) {
                const int gm = (kk + 1) * 16 + gm0;
                if (gm < evalid) {
                    const int4 nbr = *(const int4*)(nb + gm * 4);
                    const int ia = useXZ ? nbr.x : nbr.y;
                    const int ib = useXZ ? nbr.z : nbr.w;
                    gan = *(const uint4*)(xtb + (size_t)ia * CIN + gj0);
                    gcn = *(const uint4*)(xtb + (size_t)ib * CIN + gj0);
                }
            }

            // ---- compute chunk kk: 8 HMMA ----
            {
                const uint32_t akh = (uint32_t)(kk >> 2) * 8192;
                const uint32_t bkh = (uint32_t)(kk >> 2) * 16384;
                const int kc = (kk & 3) * 16;
                uint32_t ah[2][4], bf[4][2];
                #pragma unroll
                for (int mt = 0; mt < 2; ++mt) {
                    const int row = m0w + mt * 16 + a_row;
                    uint32_t off = SMEM_SWIZZLE_128B((uint32_t)(row * 128 + (kc + a_kof) * 2));
                    ldsm_x4(ah[mt][0], ah[mt][1], ah[mt][2], ah[mt][3], aB + akh + off);
                }
                #pragma unroll
                for (int nbq = 0; nbq < 2; ++nbq) {
                    const int row = n0w + nbq * 16 + b_row;
                    uint32_t off = SMEM_SWIZZLE_128B((uint32_t)(row * 128 + (kc + b_kof) * 2));
                    ldsm_x4(bf[nbq * 2][0], bf[nbq * 2][1],
                            bf[nbq * 2 + 1][0], bf[nbq * 2 + 1][1], bB + bkh + off);
                }
                #pragma unroll
                for (int mt = 0; mt < 2; ++mt)
                    #pragma unroll
                    for (int j = 0; j < 4; ++j) mma16816(acc[mt][j], ah[mt], bf[j]);
            }

            // ---- combine + STS for pass kk (sum -> slotS, abs -> slotA) ----
            if (do_fill && kk < 4) {
                const int gm = kk * 16 + gm0;
                const uint32_t off = g_koff +
                    SMEM_SWIZZLE_128B((uint32_t)(gm * 128 + (gj0 & 63) * 2));
                *(uint4*)(smem + A_H(slotS) + off) = h2_add4(ga, gc);
                *(uint4*)(smem + A_H(slotA) + off) = h2_absdiff4(ga, gc);
                ga = gan; gc = gcn;
            }
        }

        if (s < 4) {
            CP_WAIT0();
            __syncthreads();
        }
    }

    // ---------------- Epilogue: +bias, store out[b][nh*128 + o][e] ----------
    {
        const float* bsm = (const float*)(smem + SMEM_BIAS);
        float* obase = out + ((size_t)b * COUT + nh * 128) * E;
        #pragma unroll
        for (int mt = 0; mt < 2; ++mt) {
            const int r0 = m0w + mt * 16 + (lane >> 2);
            const int r1 = r0 + 8;
            const bool ok0 = r0 < evalid;
            const bool ok1 = r1 < evalid;
            #pragma unroll
            for (int j = 0; j < 4; ++j) {
                const int o = n0w + j * 8 + 2 * (lane & 3);
                const float b0 = bsm[o], b1 = bsm[o + 1];
                float* p0 = obase + (size_t)o * E;
                float* p1 = obase + (size_t)(o + 1) * E;
                if (ok0) {
                    p0[ebase + r0] = acc[mt][j][0] + b0;
                    p1[ebase + r0] = acc[mt][j][1] + b1;
                }
                if (ok1) {
                    p0[ebase + r1] = acc[mt][j][2] + b0;
                    p1[ebase + r1] = acc[mt][j][3] + b1;
                }
            }
        }
    }
}

// ============================================================================
// Launch
// ============================================================================
extern "C" void kernel_launch(void* const* d_in, const int* in_sizes, int n_in,
                              void* d_out, int out_size) {
    const float* x    = (const float*)d_in[0];
    const int*   ne   = (const int*)d_in[1];
    const float* w    = (const float*)d_in[2];
    const float* bias = (const float*)d_in[3];
    float*       out  = (float*)d_out;

    cudaFuncSetAttribute(mesh_main, cudaFuncAttributeMaxDynamicSharedMemorySize, SMEM_TOTAL);

    dim3 tgrid((E + 127) / 128, CIN / 32, BATCH);
    transpose_kernel<<<tgrid, 256>>>(x);
    wprep_kernel<<<(COUT * CIN * TAPS + 255) / 256, 256>>>(w);
    mesh_main<<<NBLOCKS, 256, SMEM_TOTAL>>>(ne, bias, out);
}